// round 16
// baseline (speedup 1.0000x reference)
#include <cuda_runtime.h>
#include <cuda_fp16.h>
#include <cstdint>

// ---------------- problem constants ----------------
#define B       64
#define N       4096
#define H       128
#define NS      8
#define ITERS   3
#define EPSA    1e-8f
#define LN_EPS  1e-5f
#define SCALE   0.125f

#define TILE_R  64
#define NB      16
#define DSTR    257
#define QSTR    66
#define WSTR    66
#define ASTR    272             // fp16 att tile stride (halves)

typedef unsigned long long ull;

// ---------------- device scratch ----------------
__device__ __half g_kh[B*N*64];
__device__ __half g_vh[B*N*64];
__device__ int    g_cnt[B*N/TILE_R];
__device__ float  g_slots[B*NS*64];
__device__ float  g_q[B*NS*64];
__device__ float  g_Pp[B*NB*NS*64];
__device__ float  g_Sp[B*NB*NS];
__device__ __half g_wkh[64*64];        // [c][d] fp16
__device__ __half g_wvh[64*64];
__device__ float4 g_WgA[64*64];
__device__ float2 g_WgB[64*64];
__device__ float2 g_W1p[64*64];
__device__ float2 g_W2p[64*64];
__device__ float2 g_Wqp[32*64];

// ---------------- helpers ----------------
__device__ __forceinline__ uint32_t smem_u32(const void* p) {
    uint32_t a;
    asm("{ .reg .u64 t; cvta.to.shared.u64 t, %1; cvt.u32.u64 %0, t; }" : "=r"(a) : "l"(p));
    return a;
}

// ---------------- merged prep + init ----------------
__global__ __launch_bounds__(256)
void k_prep_init(const float* __restrict__ Wk, const float* __restrict__ Wv,
                 const float* __restrict__ W_ih, const float* __restrict__ W_hh,
                 const float* __restrict__ W1, const float* __restrict__ W2,
                 const float* __restrict__ Wq,
                 const float* __restrict__ noise, const float* __restrict__ mu,
                 const float* __restrict__ sg,
                 const float* __restrict__ ln_s_w, const float* __restrict__ ln_s_b,
                 const float* __restrict__ bq) {
    int tid = threadIdx.x;
    int i = blockIdx.x * 256 + tid;
    if (i < 4096) {
        g_wkh[i] = __float2half_rn(Wk[i]);
        g_wvh[i] = __float2half_rn(Wv[i]);
        int d = i >> 6, x = i & 63;
        g_WgA[i] = make_float4(W_ih[x*64 + d], W_ih[(64+x)*64 + d],
                               W_ih[(128+x)*64 + d], W_hh[x*64 + d]);
        g_WgB[i] = make_float2(W_hh[(64+x)*64 + d], W_hh[(128+x)*64 + d]);
        g_W1p[i] = make_float2(W1[(2*x)*64 + d], W1[(2*x+1)*64 + d]);
        g_W2p[i] = make_float2(W2[x*128 + 2*d], W2[x*128 + 2*d + 1]);
    }
    if (i < 2048) {
        int d2 = i >> 6, dd = i & 63;
        g_Wqp[i] = make_float2(Wq[dd*64 + 2*d2], Wq[dd*64 + 2*d2 + 1]);
    }
    __shared__ float sl[512], sn[512];
    int b = blockIdx.x;
    #pragma unroll
    for (int u = 0; u < 2; ++u) {
        int t = tid + 256*u, dd = t & 63;
        float s = mu[dd] + sg[dd]*noise[b*512 + t];
        sl[t] = s;
        g_slots[b*512 + t] = s;
    }
    __syncthreads();
    {
        int wp = tid >> 5, lane = tid & 31;
        const float* p = sl + wp*64;
        float v0 = p[lane], v1 = p[lane+32];
        float s = v0 + v1;
        #pragma unroll
        for (int o = 16; o; o >>= 1) s += __shfl_xor_sync(~0u, s, o);
        float mmu = s * (1.f/64.f);
        float d0 = v0 - mmu, d1 = v1 - mmu;
        float q = d0*d0 + d1*d1;
        #pragma unroll
        for (int o = 16; o; o >>= 1) q += __shfl_xor_sync(~0u, q, o);
        float rs = rsqrtf(q * (1.f/64.f) + LN_EPS);
        sn[wp*64 + lane]      = d0*rs*ln_s_w[lane] + ln_s_b[lane];
        sn[wp*64 + lane + 32] = d1*rs*ln_s_w[lane+32] + ln_s_b[lane+32];
    }
    __syncthreads();
    #pragma unroll
    for (int u = 0; u < 2; ++u) {
        int t = tid + 256*u, j = t >> 6, dd = t & 63;
        float acc = bq[dd];
        const float2* sj2 = (const float2*)(sn + j*64);
        #pragma unroll 8
        for (int d2 = 0; d2 < 32; ++d2) {
            float2 w = *(const float2*)(Wq + dd*64 + 2*d2);
            float2 s2 = sj2[d2];
            acc += s2.x*w.x + s2.y*w.y;
        }
        g_q[b*512 + t] = acc * SCALE;
    }
}

// ---------------- K1: mask-compact + shuffle-free LN + HMMA k/v GEMM (R14 proven) ----------------
__global__ __launch_bounds__(256)
void k_ln_kv(const float* __restrict__ inputs, const int* __restrict__ mask,
             const float* __restrict__ bk, const float* __restrict__ bv,
             const float* __restrict__ lnw, const float* __restrict__ lnb) {
    __shared__ __align__(16) float xs[TILE_R*64];
    __shared__ __align__(16) char  xh[TILE_R*128];
    __shared__ __align__(4) __half wk[64*WSTR];
    __shared__ __align__(4) __half wv[64*WSTR];
    __shared__ float ps[TILE_R*4], pq[TILE_R*4];
    __shared__ float rmu[TILE_R], rrs[TILE_R];
    __shared__ int tpos[TILE_R];
    __shared__ int cmap[TILE_R];
    __shared__ int wc[2];

    int tid = threadIdx.x;
    int lane = tid & 31, warp = tid >> 5;
    size_t row0 = (size_t)blockIdx.x * TILE_R;

    for (int i = tid; i < 4096; i += 256) {
        int c = i >> 6, d = i & 63;
        wk[c*WSTR + d] = g_wkh[i];
        wv[c*WSTR + d] = g_wvh[i];
    }

    if (tid < 64) {
        int mm = mask[row0 + tid] != 0;
        unsigned bal = __ballot_sync(~0u, mm);
        if (lane == 0) wc[warp] = __popc(bal);
        tpos[tid] = mm ? __popc(bal & ((1u << lane) - 1u)) : -1;
    }
    __syncthreads();
    int act = wc[0] + wc[1];
    if (tid < 64 && tpos[tid] >= 0)
        cmap[tpos[tid] + (tid >= 32 ? wc[0] : 0)] = tid;
    if (tid == 0) g_cnt[blockIdx.x] = act;
    __syncthreads();

    {
        int rph = tid >> 4;
        int quad = tid & 15;
        for (int base = 0; base < act; base += 16) {
            int ci = base + rph;
            if (ci < act) {
                int r = cmap[ci];
                *(float4*)(xs + ci*64 + quad*4) =
                    *(const float4*)(inputs + (row0 + r)*64 + quad*4);
            }
        }
    }
    __syncthreads();

    {
        int ci = tid >> 2, q = tid & 3;
        if (ci < act) {
            const float4* p = (const float4*)(xs + ci*64 + q*16);
            float s = 0.f, ss = 0.f;
            #pragma unroll
            for (int i = 0; i < 4; ++i) {
                float4 v = p[i];
                s  += (v.x + v.y) + (v.z + v.w);
                ss += (v.x*v.x + v.y*v.y) + (v.z*v.z + v.w*v.w);
            }
            ps[ci*4 + q] = s;
            pq[ci*4 + q] = ss;
        }
    }
    __syncthreads();

    if (tid < act) {
        float s  = (ps[tid*4] + ps[tid*4+1]) + (ps[tid*4+2] + ps[tid*4+3]);
        float ss = (pq[tid*4] + pq[tid*4+1]) + (pq[tid*4+2] + pq[tid*4+3]);
        float mu  = s * (1.f/64.f);
        float var = ss * (1.f/64.f) - mu*mu;
        rmu[tid] = mu;
        rrs[tid] = rsqrtf(var + LN_EPS);
    }
    __syncthreads();

    {
        int tot = act * 8;
        for (int e = tid; e < tot; e += 256) {
            int ci = e >> 3, q = e & 7;
            float mu = rmu[ci], rs = rrs[ci];
            float4 v0 = *(float4*)(xs + ci*64 + q*8);
            float4 v1 = *(float4*)(xs + ci*64 + q*8 + 4);
            float4 w0 = __ldg((const float4*)lnw + 2*q);
            float4 w1 = __ldg((const float4*)lnw + 2*q + 1);
            float4 b0 = __ldg((const float4*)lnb + 2*q);
            float4 b1 = __ldg((const float4*)lnb + 2*q + 1);
            __half2 h[4];
            h[0] = __floats2half2_rn((v0.x - mu)*rs*w0.x + b0.x, (v0.y - mu)*rs*w0.y + b0.y);
            h[1] = __floats2half2_rn((v0.z - mu)*rs*w0.z + b0.z, (v0.w - mu)*rs*w0.w + b0.w);
            h[2] = __floats2half2_rn((v1.x - mu)*rs*w1.x + b1.x, (v1.y - mu)*rs*w1.y + b1.y);
            h[3] = __floats2half2_rn((v1.z - mu)*rs*w1.z + b1.z, (v1.w - mu)*rs*w1.w + b1.w);
            *(uint4*)(xh + ci*128 + ((q ^ (ci & 7)) << 4)) = *(uint4*)h;
        }
    }
    __syncthreads();

    {
        int wsel = warp >> 2;
        int n0 = (warp & 3) * 16;
        const __half* wh = wsel ? wv : wk;
        const float*  bias = wsel ? bv : bk;
        __half* dst = wsel ? g_vh : g_kh;

        uint32_t xh_base = smem_u32(xh);
        int j = lane >> 2, kb = (lane & 3) * 2;
        float acc[2][4][4];
        #pragma unroll
        for (int ns = 0; ns < 2; ++ns)
            #pragma unroll
            for (int mt = 0; mt < 4; ++mt)
                #pragma unroll
                for (int i = 0; i < 4; ++i) acc[ns][mt][i] = 0.f;

        #pragma unroll
        for (int ks = 0; ks < 4; ++ks) {
            uint32_t b0a = *(const uint32_t*)(wh + (n0 + j)*WSTR + 16*ks + kb);
            uint32_t b1a = *(const uint32_t*)(wh + (n0 + j)*WSTR + 16*ks + kb + 8);
            uint32_t b0b = *(const uint32_t*)(wh + (n0 + 8 + j)*WSTR + 16*ks + kb);
            uint32_t b1b = *(const uint32_t*)(wh + (n0 + 8 + j)*WSTR + 16*ks + kb + 8);
            #pragma unroll
            for (int mt = 0; mt < 4; ++mt) {
                int lr = mt*16 + (lane & 15);
                int qq = 2*ks + (lane >> 4);
                uint32_t addr = xh_base + lr*128 + ((qq ^ (lr & 7)) << 4);
                uint32_t a0, a1, a2, a3;
                asm volatile("ldmatrix.sync.aligned.m8n8.x4.shared.b16 {%0,%1,%2,%3}, [%4];"
                             : "=r"(a0), "=r"(a1), "=r"(a2), "=r"(a3) : "r"(addr));
                asm volatile("mma.sync.aligned.m16n8k16.row.col.f32.f16.f16.f32 "
                             "{%0,%1,%2,%3}, {%4,%5,%6,%7}, {%8,%9}, {%0,%1,%2,%3};"
                             : "+f"(acc[0][mt][0]), "+f"(acc[0][mt][1]),
                               "+f"(acc[0][mt][2]), "+f"(acc[0][mt][3])
                             : "r"(a0), "r"(a1), "r"(a2), "r"(a3), "r"(b0a), "r"(b1a));
                asm volatile("mma.sync.aligned.m16n8k16.row.col.f32.f16.f16.f32 "
                             "{%0,%1,%2,%3}, {%4,%5,%6,%7}, {%8,%9}, {%0,%1,%2,%3};"
                             : "+f"(acc[1][mt][0]), "+f"(acc[1][mt][1]),
                               "+f"(acc[1][mt][2]), "+f"(acc[1][mt][3])
                             : "r"(a0), "r"(a1), "r"(a2), "r"(a3), "r"(b0b), "r"(b1b));
            }
        }

        int trow = lane >> 2;
        #pragma unroll
        for (int ns = 0; ns < 2; ++ns) {
            int c = n0 + ns*8 + (lane & 3)*2;
            float bx = __ldg(bias + c), by = __ldg(bias + c + 1);
            #pragma unroll
            for (int mt = 0; mt < 4; ++mt) {
                int r0 = mt*16 + trow;
                int r1 = r0 + 8;
                if (r0 < act) {
                    __half2 hv = __floats2half2_rn(acc[ns][mt][0] + bx, acc[ns][mt][1] + by);
                    *(__half2*)(dst + (row0 + r0)*64 + c) = hv;
                }
                if (r1 < act) {
                    __half2 hv = __floats2half2_rn(acc[ns][mt][2] + bx, acc[ns][mt][3] + by);
                    *(__half2*)(dst + (row0 + r1)*64 + c) = hv;
                }
            }
        }
    }
}

// ---------------- LN over slot rows ----------------
__device__ __forceinline__ void lnrows(const float* in, float* out,
                                       const float* __restrict__ w,
                                       const float* __restrict__ bia, int tid, int nrows) {
    int wp = tid >> 5, lane = tid & 31;
    if (wp >= nrows) return;
    const float* p = in + wp*64;
    float v0 = p[lane], v1 = p[lane+32];
    float s = v0 + v1;
    #pragma unroll
    for (int o = 16; o; o >>= 1) s += __shfl_xor_sync(~0u, s, o);
    float mu = s * (1.f/64.f);
    float d0 = v0 - mu, d1 = v1 - mu;
    float q = d0*d0 + d1*d1;
    #pragma unroll
    for (int o = 16; o; o >>= 1) q += __shfl_xor_sync(~0u, q, o);
    float rs = rsqrtf(q * (1.f/64.f) + LN_EPS);
    out[wp*64 + lane]      = d0*rs*w[lane] + bia[lane];
    out[wp*64 + lane + 32] = d1*rs*w[lane+32] + bia[lane+32];
}

// ---------------- attention: HMMA phase A + HMMA phase C (R15 proven) ----------------
__global__ __launch_bounds__(256)
void k_attn() {
    __shared__ __align__(16) char sbuf[32*1024];
    __shared__ __align__(16) char dU[16*ASTR*2];
    __shared__ __align__(4)  __half qh[8*QSTR];
    __shared__ int cnts[4];

    float*  dots = (float*)dU;
    __half* attH = (__half*)dU;

    int b = blockIdx.y, chunk = blockIdx.x;
    int tid = threadIdx.x;
    int warp = tid >> 5, lane = tid & 31;

    if (tid < 4) cnts[tid] = g_cnt[b*(N/TILE_R) + chunk*4 + tid];

    {
        const uint4* src = (const uint4*)(g_kh + ((size_t)b*N + chunk*256)*64);
        #pragma unroll
        for (int e0 = 0; e0 < 2048; e0 += 256) {
            int e = e0 + tid;
            int ci = e >> 3, q = e & 7;
            uint4 v = __ldg(src + e);
            *(uint4*)(sbuf + ci*128 + ((q ^ (ci & 7)) << 4)) = v;
        }
    }
    for (int e = tid; e < 512; e += 256) {
        int j = e >> 6, d = e & 63;
        qh[j*QSTR + d] = __float2half_rn(g_q[b*512 + e]);
    }
    __syncthreads();

    {
        uint32_t stg_base = smem_u32(sbuf);
        int R0 = warp * 32;
        float d0[4] = {0.f,0.f,0.f,0.f};
        float d1[4] = {0.f,0.f,0.f,0.f};
        int j = lane >> 2, kb = (lane & 3) * 2;
        #pragma unroll
        for (int ks = 0; ks < 4; ++ks) {
            uint32_t b0 = *(const uint32_t*)(qh + j*QSTR + 16*ks + kb);
            uint32_t b1 = *(const uint32_t*)(qh + j*QSTR + 16*ks + kb + 8);
            #pragma unroll
            for (int tile = 0; tile < 2; ++tile) {
                int lr = R0 + tile*16 + (lane & 15);
                int qq = 2*ks + (lane >> 4);
                uint32_t addr = stg_base + lr*128 + ((qq ^ (lr & 7)) << 4);
                uint32_t a0, a1, a2, a3;
                asm volatile("ldmatrix.sync.aligned.m8n8.x4.shared.b16 {%0,%1,%2,%3}, [%4];"
                             : "=r"(a0), "=r"(a1), "=r"(a2), "=r"(a3) : "r"(addr));
                float* dd = tile ? d1 : d0;
                asm volatile("mma.sync.aligned.m16n8k16.row.col.f32.f16.f16.f32 "
                             "{%0,%1,%2,%3}, {%4,%5,%6,%7}, {%8,%9}, {%0,%1,%2,%3};"
                             : "+f"(dd[0]), "+f"(dd[1]), "+f"(dd[2]), "+f"(dd[3])
                             : "r"(a0), "r"(a1), "r"(a2), "r"(a3), "r"(b0), "r"(b1));
            }
        }
        int s = warp >> 1;
        int rbase = (warp & 1) * 32;
        int trow = lane >> 2;
        int col = (lane & 3) * 2;
        #pragma unroll
        for (int tile = 0; tile < 2; ++tile) {
            float* dd = tile ? d1 : d0;
            int r = rbase + tile*16 + trow;
            dots[(col  )*DSTR + s*64 + r    ] = dd[0];
            dots[(col+1)*DSTR + s*64 + r    ] = dd[1];
            dots[(col  )*DSTR + s*64 + r + 8] = dd[2];
            dots[(col+1)*DSTR + s*64 + r + 8] = dd[3];
        }
    }
    __syncthreads();

    float av[8];
    {
        int s = tid >> 6, r = tid & 63;
        int act = cnts[s];
        if (r < act) {
            float d[8];
            #pragma unroll
            for (int j2 = 0; j2 < 8; ++j2) d[j2] = dots[j2*DSTR + tid];
            float m = d[0];
            #pragma unroll
            for (int j2 = 1; j2 < 8; ++j2) m = fmaxf(m, d[j2]);
            float e[8], sum = 0.f;
            #pragma unroll
            for (int j2 = 0; j2 < 8; ++j2) { e[j2] = __expf(d[j2] - m); sum += e[j2]; }
            float inv = __fdividef(1.f, sum);
            #pragma unroll
            for (int j2 = 0; j2 < 8; ++j2) av[j2] = e[j2]*inv + EPSA;
        } else {
            #pragma unroll
            for (int j2 = 0; j2 < 8; ++j2) av[j2] = 0.f;
        }
    }
    {
        const uint4* src = (const uint4*)(g_vh + ((size_t)b*N + chunk*256)*64);
        #pragma unroll
        for (int e0 = 0; e0 < 2048; e0 += 256) {
            int e = e0 + tid;
            int ci = e >> 3, q = e & 7;
            uint4 v = __ldg(src + e);
            *(uint4*)(sbuf + ci*128 + ((q ^ (ci & 7)) << 4)) = v;
        }
    }
    __syncthreads();

    #pragma unroll
    for (int j2 = 0; j2 < 8; ++j2)
        attH[j2*ASTR + tid] = __float2half_rn(av[j2]);
    for (int e = tid; e < 8*ASTR; e += 256)
        attH[8*ASTR + e] = __ushort_as_half(0);
    __syncthreads();

    {
        const __half2* ap = (const __half2*)(attH + warp*ASTR);
        float s = 0.f;
        #pragma unroll
        for (int i = 0; i < 4; ++i) {
            float2 f = __half22float2(ap[lane + 32*i]);
            s += f.x + f.y;
        }
        #pragma unroll
        for (int o = 16; o; o >>= 1) s += __shfl_xor_sync(~0u, s, o);
        if (lane == 0) g_Sp[(b*NB + chunk)*8 + warp] = s;
    }

    {
        uint32_t vbase = smem_u32(sbuf);
        uint32_t abase = smem_u32(attH);
        float acc[4] = {0.f, 0.f, 0.f, 0.f};
        int qcol = warp;
        #pragma unroll
        for (int ks = 0; ks < 16; ++ks) {
            uint32_t aaddr = abase + (uint32_t)((lane & 15)*ASTR + ks*16 + ((lane >> 4) << 3)) * 2u;
            uint32_t a0, a1, a2, a3;
            asm volatile("ldmatrix.sync.aligned.m8n8.x4.shared.b16 {%0,%1,%2,%3}, [%4];"
                         : "=r"(a0), "=r"(a1), "=r"(a2), "=r"(a3) : "r"(aaddr));
            int krow = ks*16 + (lane & 15);
            uint32_t baddr = vbase + krow*128 + ((qcol ^ (krow & 7)) << 4);
            uint32_t bb0, bb1;
            asm volatile("ldmatrix.sync.aligned.m8n8.x2.trans.shared.b16 {%0,%1}, [%2];"
                         : "=r"(bb0), "=r"(bb1) : "r"(baddr));
            asm volatile("mma.sync.aligned.m16n8k16.row.col.f32.f16.f16.f32 "
                         "{%0,%1,%2,%3}, {%4,%5,%6,%7}, {%8,%9}, {%0,%1,%2,%3};"
                         : "+f"(acc[0]), "+f"(acc[1]), "+f"(acc[2]), "+f"(acc[3])
                         : "r"(a0), "r"(a1), "r"(a2), "r"(a3), "r"(bb0), "r"(bb1));
        }
        int slot = lane >> 2;
        int c = warp*8 + (lane & 3)*2;
        float* pp = g_Pp + ((size_t)b*NB + chunk)*512 + slot*64 + c;
        pp[0] = acc[0];
        pp[1] = acc[1];
    }
}

// ---------------- slot update: K-split across 512 threads ----------------
__global__ __launch_bounds__(512, 1)
void k_update(const float* __restrict__ b_ih, const float* __restrict__ b_hh,
              const float* __restrict__ b1, const float* __restrict__ b2,
              const float* __restrict__ ln_ff_w, const float* __restrict__ ln_ff_b,
              const float* __restrict__ ln_s_w, const float* __restrict__ ln_s_b,
              const float* __restrict__ bq,
              float* __restrict__ d_out, int last) {
    __shared__ float upd[256], prev[256], snew[256], ffs[256], hid[512], sfin[256], Ssm[4];
    __shared__ float part[2048];
    int b = blockIdx.y, half = blockIdx.x, tid = threadIdx.x;
    int lo = tid >> 8;            // K-half 0/1
    int t  = tid & 255;
    int j0 = half * 4;
    int j = t >> 6, dd = t & 63;
    int J = j0 + j;

    if (tid < 4) {
        float v[NB];
        const float* sp = g_Sp + b*NB*8 + j0 + tid;
        #pragma unroll
        for (int p = 0; p < NB; ++p) v[p] = sp[p*8];
        float s = 0.f;
        #pragma unroll
        for (int p = 0; p < NB; ++p) s += v[p];
        Ssm[tid] = s;
    }
    // Pp reduce: each (t, lo) sums 8 partials
    {
        float v[8];
        const float* pp = g_Pp + (size_t)b*NB*512 + (lo*8)*512 + J*64 + dd;
        #pragma unroll
        for (int p = 0; p < 8; ++p) v[p] = pp[p*512];
        float s = 0.f;
        #pragma unroll
        for (int p = 0; p < 8; ++p) s += v[p];
        part[tid] = s;
        if (lo == 0) prev[t] = g_slots[b*512 + J*64 + dd];
    }
    __syncthreads();
    if (lo == 0) upd[t] = (part[t] + part[t + 256]) / Ssm[j];
    __syncthreads();

    // GRU: d range [lo*32, lo*32+32), 4 batches of 8
    {
        const float* uj = upd + j*64 + lo*32;
        const float* hj = prev + j*64 + lo*32;
        float xr = 0.f, xz = 0.f, xn = 0.f, hr = 0.f, hz = 0.f, hn = 0.f;
        #pragma unroll
        for (int db = 0; db < 32; db += 8) {
            float4 wa8[8];
            float2 wb8[8];
            #pragma unroll
            for (int u = 0; u < 8; ++u) wa8[u] = __ldg(g_WgA + (lo*32 + db + u)*64 + dd);
            #pragma unroll
            for (int u = 0; u < 8; ++u) wb8[u] = __ldg(g_WgB + (lo*32 + db + u)*64 + dd);
            #pragma unroll
            for (int u = 0; u < 8; ++u) {
                float uu = uj[db+u], hh = hj[db+u];
                xr += uu*wa8[u].x; xz += uu*wa8[u].y; xn += uu*wa8[u].z;
                hr += hh*wa8[u].w; hz += hh*wb8[u].x; hn += hh*wb8[u].y;
            }
        }
        part[tid]        = xr + hr;
        part[512 + tid]  = xz + hz;
        part[1024 + tid] = xn;
        part[1536 + tid] = hn;
    }
    __syncthreads();
    if (lo == 0) {
        float s0 = part[t] + part[t+256] + b_ih[dd] + b_hh[dd];
        float s1 = part[512+t] + part[512+t+256] + b_ih[64+dd] + b_hh[64+dd];
        float s2 = part[1024+t] + part[1024+t+256] + b_ih[128+dd];
        float s3 = part[1536+t] + part[1536+t+256] + b_hh[128+dd];
        float rg = 1.f/(1.f + __expf(-s0));
        float zg = 1.f/(1.f + __expf(-s1));
        float t2 = __expf(2.f*(s2 + rg*s3));
        float nn = 1.f - 2.f/(t2 + 1.f);
        snew[t] = (1.f - zg)*nn + zg*prev[t];
    }
    __syncthreads();
    lnrows(snew, ffs, ln_ff_w, ln_ff_b, tid, 4);
    __syncthreads();
    // MLP1: (j,h2) output pair; partial over d in [lo*32, +32), 2 batches of 16
    {
        int h2 = dd;
        float a0 = 0.f, a1 = 0.f;
        const float* fj = ffs + j*64 + lo*32;
        #pragma unroll
        for (int db = 0; db < 32; db += 16) {
            float2 w8[16];
            #pragma unroll
            for (int u = 0; u < 16; ++u) w8[u] = __ldg(g_W1p + (lo*32 + db + u)*64 + h2);
            #pragma unroll
            for (int u = 0; u < 16; ++u) {
                float f = fj[db+u];
                a0 += f*w8[u].x; a1 += f*w8[u].y;
            }
        }
        part[tid]       = a0;
        part[512 + tid] = a1;
    }
    __syncthreads();
    if (lo == 0) {
        float a0 = part[t] + part[t+256] + b1[2*dd];
        float a1 = part[512+t] + part[512+t+256] + b1[2*dd+1];
        hid[j*128 + 2*dd]   = fmaxf(a0, 0.f);
        hid[j*128 + 2*dd+1] = fmaxf(a1, 0.f);
    }
    __syncthreads();
    // MLP2: partial over h2 in [lo*32, +32), 2 batches of 16
    {
        float acc = 0.f;
        const float2* hj2 = (const float2*)(hid + j*128) + lo*32;
        #pragma unroll
        for (int hb = 0; hb < 32; hb += 16) {
            float2 w8[16];
            #pragma unroll
            for (int u = 0; u < 16; ++u) w8[u] = __ldg(g_W2p + (lo*32 + hb + u)*64 + dd);
            #pragma unroll
            for (int u = 0; u < 16; ++u) {
                float2 hv = hj2[hb+u];
                acc += hv.x*w8[u].x + hv.y*w8[u].y;
            }
        }
        part[tid] = acc;
    }
    __syncthreads();
    if (lo == 0) {
        float o = snew[t] + part[t] + part[t+256] + b2[dd];
        sfin[t] = o;
        g_slots[b*512 + J*64 + dd] = o;
        if (last) d_out[b*512 + J*64 + dd] = o;
    }
    if (!last) {
        __syncthreads();
        lnrows(sfin, ffs, ln_s_w, ln_s_b, tid, 4);
        __syncthreads();
        // qproj: partial over d2 in [lo*16, +16), 1 batch of 16
        {
            float acc = 0.f;
            const float2* sj2 = (const float2*)(ffs + j*64) + lo*16;
            float2 w8[16];
            #pragma unroll
            for (int u = 0; u < 16; ++u) w8[u] = __ldg(g_Wqp + (lo*16 + u)*64 + dd);
            #pragma unroll
            for (int u = 0; u < 16; ++u) {
                float2 s2 = sj2[u];
                acc += s2.x*w8[u].x + s2.y*w8[u].y;
            }
            part[tid] = acc;
        }
        __syncthreads();
        if (lo == 0)
            g_q[b*512 + J*64 + dd] = (part[t] + part[t+256] + bq[dd]) * SCALE;
    }
}

// ---------------- launch ----------------
extern "C" void kernel_launch(void* const* d_in, const int* in_sizes, int n_in,
                              void* d_out, int out_size) {
    const float* inputs     = (const float*)d_in[0];
    const int*   mask       = (const int*)  d_in[1];
    const float* noise      = (const float*)d_in[2];
    const float* slots_mu   = (const float*)d_in[3];
    const float* slots_sig  = (const float*)d_in[4];
    const float* Wq         = (const float*)d_in[5];
    const float* bq         = (const float*)d_in[6];
    const float* Wk         = (const float*)d_in[7];
    const float* bk         = (const float*)d_in[8];
    const float* Wv         = (const float*)d_in[9];
    const float* bv         = (const float*)d_in[10];
    const float* W_ih       = (const float*)d_in[11];
    const float* b_ih       = (const float*)d_in[12];
    const float* W_hh       = (const float*)d_in[13];
    const float* b_hh       = (const float*)d_in[14];
    const float* W1         = (const float*)d_in[15];
    const float* b1         = (const float*)d_in[16];
    const float* W2         = (const float*)d_in[17];
    const float* b2         = (const float*)d_in[18];
    const float* ln_in_w    = (const float*)d_in[19];
    const float* ln_in_b    = (const float*)d_in[20];
    const float* ln_s_w     = (const float*)d_in[21];
    const float* ln_s_b     = (const float*)d_in[22];
    const float* ln_ff_w    = (const float*)d_in[23];
    const float* ln_ff_b    = (const float*)d_in[24];
    float* out = (float*)d_out;

    k_prep_init<<<64, 256>>>(Wk, Wv, W_ih, W_hh, W1, W2, Wq,
                             noise, slots_mu, slots_sig, ln_s_w, ln_s_b, bq);
    k_ln_kv<<<(B*N)/TILE_R, 256>>>(inputs, mask, bk, bv, ln_in_w, ln_in_b);
    for (int it = 0; it < ITERS; ++it) {
        k_attn<<<dim3(NB, B), 256>>>();
        k_update<<<dim3(2, B), 512>>>(b_ih, b_hh, b1, b2, ln_ff_w, ln_ff_b,
                                      ln_s_w, ln_s_b, bq, out, it == ITERS-1 ? 1 : 0);
    }
}